// round 3
// baseline (speedup 1.0000x reference)
#include <cuda_runtime.h>

#define NN 50000
#define EE 300000
#define ETOT (3 * EE)
#define TT 3
#define CC 2
#define HIDD 64
#define NBLK ((NN + 255) / 256)   // 196 scan blocks

// Scratch (no allocation allowed).
__device__ __align__(256) float g_H0[CC * NN * HIDD];
__device__ __align__(256) float g_H1[CC * NN * HIDD];
__device__ __align__(256) float g_X0[CC * NN * HIDD];
__device__ __align__(256) float g_Xmid[NN * HIDD];
__device__ float g_filt[2][2][CC][TT];

// CSR scratch
__device__ int g_cnt[NN];
__device__ int g_off[NN + 1];
__device__ int g_cur[NN];
__device__ int g_bsum[256];
__device__ int g_bscan[256];
__device__ __align__(256) uint2 g_csr[ETOT];   // {col | (etype<<16), val bits}

// ---------------------------------------------------------------------------
__global__ void filt_kernel(const float* __restrict__ lw0,
                            const float* __restrict__ lw1) {
    int t = threadIdx.x;
    if (t >= 8) return;
    int b = t >> 2, l = (t >> 1) & 1, c = t & 1;
    const float* lw = (b ? lw1 : lw0) + (l * CC + c) * TT;
    float a0 = lw[0], a1 = lw[1], a2 = lw[2];
    float m = fmaxf(a0, fmaxf(a1, a2));
    float e0 = __expf(a0 - m), e1 = __expf(a1 - m), e2 = __expf(a2 - m);
    float s = 1.0f / (e0 + e1 + e2);
    g_filt[b][l][c][0] = e0 * s;
    g_filt[b][l][c][1] = e1 * s;
    g_filt[b][l][c][2] = e2 * s;
}

// ---------------------------------------------------------------------------
__global__ void zero_cnt_kernel() {
    int i = blockIdx.x * blockDim.x + threadIdx.x;
    if (i < NN) g_cnt[i] = 0;
}

__device__ __forceinline__ void pick_edge(unsigned e,
                                          const int* ei0, const int* ei1, const int* ei2,
                                          const float* ev0, const float* ev1, const float* ev2,
                                          const int** ei, const float** ev,
                                          int* j, unsigned* local) {
    if (e < EE)           { *ei = ei0; *ev = ev0; *j = 0; *local = e; }
    else if (e < 2u * EE) { *ei = ei1; *ev = ev1; *j = 1; *local = e - EE; }
    else                  { *ei = ei2; *ev = ev2; *j = 2; *local = e - 2u * EE; }
}

__global__ void hist_kernel(const int* __restrict__ ei0, const int* __restrict__ ei1,
                            const int* __restrict__ ei2) {
    unsigned e = blockIdx.x * blockDim.x + threadIdx.x;
    if (e >= ETOT) return;
    const int* ei; const float* ev; int j; unsigned local;
    pick_edge(e, ei0, ei1, ei2, nullptr, nullptr, nullptr, &ei, &ev, &j, &local);
    atomicAdd(&g_cnt[__ldg(ei + local)], 1);
}

__global__ void scanA_kernel() {
    __shared__ int s[256];
    int i = blockIdx.x * 256 + threadIdx.x;
    int v = (i < NN) ? g_cnt[i] : 0;
    s[threadIdx.x] = v;
    __syncthreads();
#pragma unroll
    for (int o = 128; o > 0; o >>= 1) {
        if (threadIdx.x < o) s[threadIdx.x] += s[threadIdx.x + o];
        __syncthreads();
    }
    if (threadIdx.x == 0) g_bsum[blockIdx.x] = s[0];
}

__global__ void scanB_kernel() {
    __shared__ int s[256];
    int t = threadIdx.x;
    int v = (t < NBLK) ? g_bsum[t] : 0;
    s[t] = v;
    __syncthreads();
#pragma unroll
    for (int o = 1; o < 256; o <<= 1) {
        int x = (t >= o) ? s[t - o] : 0;
        __syncthreads();
        s[t] += x;
        __syncthreads();
    }
    g_bscan[t] = s[t] - v;   // exclusive
    if (t == 0) g_off[NN] = ETOT;
}

__global__ void scanC_kernel() {
    __shared__ int s[256];
    int t = threadIdx.x;
    int i = blockIdx.x * 256 + t;
    int v = (i < NN) ? g_cnt[i] : 0;
    s[t] = v;
    __syncthreads();
#pragma unroll
    for (int o = 1; o < 256; o <<= 1) {
        int x = (t >= o) ? s[t - o] : 0;
        __syncthreads();
        s[t] += x;
        __syncthreads();
    }
    if (i < NN) {
        int excl = s[t] - v + g_bscan[blockIdx.x];
        g_off[i] = excl;
        g_cur[i] = excl;
    }
}

__global__ void scatter_kernel(const int* __restrict__ ei0, const int* __restrict__ ei1,
                               const int* __restrict__ ei2,
                               const float* __restrict__ ev0, const float* __restrict__ ev1,
                               const float* __restrict__ ev2) {
    unsigned e = blockIdx.x * blockDim.x + threadIdx.x;
    if (e >= ETOT) return;
    const int* ei; const float* ev; int j; unsigned local;
    pick_edge(e, ei0, ei1, ei2, ev0, ev1, ev2, &ei, &ev, &j, &local);
    int row = __ldg(ei + local);
    int col = __ldg(ei + EE + local);
    float val = __ldg(ev + local);
    int pos = atomicAdd(&g_cur[row], 1);
    g_csr[pos] = make_uint2((unsigned)col | ((unsigned)j << 16), __float_as_uint(val));
}

// ---------------------------------------------------------------------------
// Persistent projection GEMM: H[c] = Xin @ Ws[c]; weights loaded ONCE per block.
// block dim3(64,16); grid = 2*148.
__global__ void gemm_proj_kernel(const float* __restrict__ Xparam,
                                 const float* __restrict__ Ws, int blk) {
    const float* Xin = (blk == 0) ? Xparam : g_Xmid;
    __shared__ float sW[CC * 64 * 64];
    __shared__ float sX[16][64];
    int tx = threadIdx.x, ty = threadIdx.y;
    int tid = ty * 64 + tx;
    for (int i = tid; i < CC * 4096; i += 1024) sW[i] = Ws[i];
    __syncthreads();
    for (int g = blockIdx.x; g < NN / 16; g += gridDim.x) {
        int n = g * 16 + ty;
        sX[ty][tx] = Xin[(size_t)n * 64 + tx];
        __syncthreads();
#pragma unroll
        for (int c = 0; c < CC; c++) {
            float acc = 0.0f;
#pragma unroll
            for (int k = 0; k < 64; k++)
                acc = fmaf(sX[ty][k], sW[c * 4096 + k * 64 + tx], acc);
            size_t o = ((size_t)c * NN + n) * 64 + tx;
            g_H0[o] = acc;
            g_X0[o] = acc;
        }
        __syncthreads();
    }
}

// ---------------------------------------------------------------------------
// CSR SpMM: 2 rows per warp, lanes = 2 channels x 16 float4-chunks.
// Entry loads are index-addressed (pipeline ahead); gathers from both row
// streams interleave for ~8 outstanding loads per warp with unroll 4.
__global__ void spmm_csr_kernel(int blk, int layer, int srcbuf) {
    unsigned w = (blockIdx.x * blockDim.x + threadIdx.x) >> 5;
    unsigned r0 = w * 2u;
    if (r0 >= NN) return;
    unsigned r1 = r0 + 1;
    int lane = threadIdx.x & 31;
    int c = lane >> 4;
    int chunk = lane & 15;

    float f0 = g_filt[blk][layer][c][0];
    float f1 = g_filt[blk][layer][c][1];
    float f2 = g_filt[blk][layer][c][2];

    const float* src = srcbuf ? g_H1 : g_H0;
    float* dst = srcbuf ? g_H0 : g_H1;
    const float4* srcb = (const float4*)(src + (size_t)c * NN * 64);

    int s0 = __ldg(&g_off[r0]);
    int s1 = __ldg(&g_off[r1]);
    int e1 = __ldg(&g_off[r1 + 1]);
    int n0 = s1 - s0;
    int n1 = e1 - s1;
    int nmax = max(n0, n1);

    float4 a0 = make_float4(0.f, 0.f, 0.f, 0.f);
    float4 a1 = make_float4(0.f, 0.f, 0.f, 0.f);

#pragma unroll 4
    for (int i = 0; i < nmax; i++) {
        if (i < n0) {
            uint2 t = __ldg(&g_csr[s0 + i]);
            int et = (int)(t.x >> 16);
            float coef = __uint_as_float(t.y) * (et == 0 ? f0 : (et == 1 ? f1 : f2));
            float4 v = __ldg(srcb + (size_t)(t.x & 0xFFFFu) * 16 + chunk);
            a0.x = fmaf(coef, v.x, a0.x);
            a0.y = fmaf(coef, v.y, a0.y);
            a0.z = fmaf(coef, v.z, a0.z);
            a0.w = fmaf(coef, v.w, a0.w);
        }
        if (i < n1) {
            uint2 t = __ldg(&g_csr[s1 + i]);
            int et = (int)(t.x >> 16);
            float coef = __uint_as_float(t.y) * (et == 0 ? f0 : (et == 1 ? f1 : f2));
            float4 v = __ldg(srcb + (size_t)(t.x & 0xFFFFu) * 16 + chunk);
            a1.x = fmaf(coef, v.x, a1.x);
            a1.y = fmaf(coef, v.y, a1.y);
            a1.z = fmaf(coef, v.z, a1.z);
            a1.w = fmaf(coef, v.w, a1.w);
        }
    }
    *((float4*)(dst + ((size_t)c * NN + r0) * 64) + chunk) = a0;
    *((float4*)(dst + ((size_t)c * NN + r1) * 64) + chunk) = a1;
}

// ---------------------------------------------------------------------------
// Persistent teleport-mix + Linear(128->64) + ReLU; weights loaded once.
__global__ void mix_lin_kernel(const float* __restrict__ linW,
                               const float* __restrict__ linb,
                               float* __restrict__ outp, int blk) {
    __shared__ float sW[128 * 64];
    __shared__ float sb[64];
    __shared__ float shm[16][128];
    int tx = threadIdx.x, ty = threadIdx.y;
    int tid = ty * 64 + tx;
#pragma unroll
    for (int i = 0; i < 8; i++)
        sW[tid + i * 1024] = linW[tid + i * 1024];
    if (tid < 64) sb[tid] = linb[tid];
    __syncthreads();
    for (int g = blockIdx.x; g < NN / 16; g += gridDim.x) {
        int n = g * 16 + ty;
#pragma unroll
        for (int c = 0; c < CC; c++) {
            size_t o = ((size_t)c * NN + n) * 64 + tx;
            float x0 = g_X0[o];
            float h = g_H0[o];
            float t = 0.5f * x0 + 0.5f * h;            // BETA = 0.5
            t = fmaxf(t, 0.0f);
            shm[ty][c * 64 + tx] = 0.8f * t + 0.2f * x0;  // TP = 0.8
        }
        __syncthreads();
        float acc = sb[tx];
#pragma unroll
        for (int k = 0; k < 128; k++)
            acc = fmaf(shm[ty][k], sW[k * 64 + tx], acc);
        acc = fmaxf(acc, 0.0f);
        float* op = (blk == 0) ? g_Xmid : outp;
        op[(size_t)n * 64 + tx] = acc;
        __syncthreads();
    }
}

// ---------------------------------------------------------------------------
extern "C" void kernel_launch(void* const* d_in, const int* in_sizes, int n_in,
                              void* d_out, int out_size) {
    const float* X     = (const float*)d_in[0];
    const float* ev0   = (const float*)d_in[1];
    const float* ev1   = (const float*)d_in[2];
    const float* ev2   = (const float*)d_in[3];
    const float* Ws0   = (const float*)d_in[4];
    const float* Ws1   = (const float*)d_in[5];
    const float* lw0   = (const float*)d_in[6];
    const float* lw1   = (const float*)d_in[7];
    const float* linW0 = (const float*)d_in[8];
    const float* linb0 = (const float*)d_in[9];
    const float* linW1 = (const float*)d_in[10];
    const float* linb1 = (const float*)d_in[11];
    const int* ei0     = (const int*)d_in[12];
    const int* ei1     = (const int*)d_in[13];
    const int* ei2     = (const int*)d_in[14];
    float* out = (float*)d_out;

    filt_kernel<<<1, 32>>>(lw0, lw1);

    // CSR build (reused by all 4 SpMMs)
    const int egrid = (ETOT + 255) / 256;
    zero_cnt_kernel<<<(NN + 255) / 256, 256>>>();
    hist_kernel<<<egrid, 256>>>(ei0, ei1, ei2);
    scanA_kernel<<<NBLK, 256>>>();
    scanB_kernel<<<1, 256>>>();
    scanC_kernel<<<NBLK, 256>>>();
    scatter_kernel<<<egrid, 256>>>(ei0, ei1, ei2, ev0, ev1, ev2);

    const int spmm_grid = ((NN / 2) * 32 + 255) / 256;   // 2 rows per warp
    dim3 tb(64, 16);
    const int pgrid = 296;   // 2 * 148 persistent blocks

    for (int blk = 0; blk < 2; blk++) {
        gemm_proj_kernel<<<pgrid, tb>>>(X, blk ? Ws1 : Ws0, blk);
        spmm_csr_kernel<<<spmm_grid, 256>>>(blk, 0, 0);   // H0 -> H1
        spmm_csr_kernel<<<spmm_grid, 256>>>(blk, 1, 1);   // H1 -> H0
        mix_lin_kernel<<<pgrid, tb>>>(blk ? linW1 : linW0, blk ? linb1 : linb0, out, blk);
    }
}